// round 15
// baseline (speedup 1.0000x reference)
#include <cuda_runtime.h>
#include <cuda_bf16.h>
#include <cstdint>

// CRF log-partition forward scan on tensor cores (mma.sync m16n8k16 bf16).
// B=64 batches, one block (128 threads / 4 warps = 1 per SMSP) per batch.
// Linear-domain recurrence u_t = diag(exp(e_t)) * expT^T * u_{t-1}.
// Chain: bar -> UNCONDITIONAL broadcast LDS.128 x4 (every lane loads via
// lane&3; lanes 4-31 feed valid-but-unused B cols 1-7 -- removes the
// BSSY/BSYNC branch envelope from the chain) -> [LDS shadow: renorm fold +
// quad-split exp regen (2 MUFU + 2 SHFL) + 2 LDG prefetch] -> 16 HMMA
// (4 chains x 2 m-tiles, C=0 seeded) -> add tree -> d*pe -> SHF>>16
// bf16-truncation store (bias pre-cancelled via pe *= 1+2^-9) -> STS x4 ->
// (1/8-step renorm publish) -> bar.
// Renorm every 8 steps, stale-applied, sampled max; target 2^-30.

static constexpr int Bb = 64;
static constexpr int Ll = 512;
static constexpr int Nn = 128;

__device__ __forceinline__ uint32_t pkbf(float lo, float hi) {
    unsigned short l = __bfloat16_as_ushort(__float2bfloat16(lo));
    unsigned short h = __bfloat16_as_ushort(__float2bfloat16(hi));
    return (uint32_t)l | ((uint32_t)h << 16);
}

// b16 index of row r in the B-fragment-permuted u layout
__device__ __forceinline__ int permb(int r) {
    int kt = r >> 4, kr = r & 15;
    int half = kr >> 3, tsel = (kr & 7) >> 1, lohi = kr & 1;
    return tsel * 32 + kt * 4 + half * 2 + lohi;
}

__device__ __forceinline__ uint32_t smem_u32(const void* p) {
    uint32_t a;
    asm("{ .reg .u64 t; cvta.to.shared.u64 t, %1; cvt.u32.u64 %0, t; }"
        : "=r"(a) : "l"(p));
    return a;
}

// acc += A*B
__device__ __forceinline__ void mma_acc(float& d0, float& d1, float& d2, float& d3,
                                        uint32_t a0, uint32_t a1, uint32_t a2,
                                        uint32_t a3, uint32_t b0, uint32_t b1) {
    asm volatile(
        "mma.sync.aligned.m16n8k16.row.col.f32.bf16.bf16.f32 "
        "{%0,%1,%2,%3}, {%4,%5,%6,%7}, {%8,%9}, {%0,%1,%2,%3};"
        : "+f"(d0), "+f"(d1), "+f"(d2), "+f"(d3)
        : "r"(a0), "r"(a1), "r"(a2), "r"(a3), "r"(b0), "r"(b1));
}

// acc = A*B (C operand pinned to z: no accumulator-init MOVs)
__device__ __forceinline__ void mma_zc(float& d0, float& d1, float& d2, float& d3,
                                       uint32_t a0, uint32_t a1, uint32_t a2,
                                       uint32_t a3, uint32_t b0, uint32_t b1,
                                       float z) {
    asm volatile(
        "mma.sync.aligned.m16n8k16.row.col.f32.bf16.bf16.f32 "
        "{%0,%1,%2,%3}, {%4,%5,%6,%7}, {%8,%9}, {%10,%10,%10,%10};"
        : "=f"(d0), "=f"(d1), "=f"(d2), "=f"(d3)
        : "r"(a0), "r"(a1), "r"(a2), "r"(a3), "r"(b0), "r"(b1), "f"(z));
}

__global__ __launch_bounds__(128, 1)
void crf_forward_kernel(const float* __restrict__ emissions,
                        const float* __restrict__ transitions,
                        const float* __restrict__ start_t,
                        const float* __restrict__ end_t,
                        const int*   __restrict__ lengths,
                        float*       __restrict__ out)
{
    const int b    = blockIdx.x;
    const int j    = threadIdx.x;
    const int lane = j & 31;
    const int wid  = j >> 5;

    __shared__ __align__(16) unsigned short ubuf[2][Nn];  // bf16 bits, permuted
    __shared__ float red[8];   // [0..3] renorm samples, [4..7] final reduce

    const float* E = emissions + (size_t)b * Ll * Nn;

    // ---- stationary A fragments: A[m][k] = exp(transitions[k][m]) ----
    const int g  = lane >> 2;
    const int cq = (lane & 3) * 2;
    uint32_t A[2][8][4];
#pragma unroll
    for (int mt = 0; mt < 2; ++mt) {
        const int r0 = wid * 32 + mt * 16 + g;
#pragma unroll
        for (int kt = 0; kt < 8; ++kt) {
            const int c0 = kt * 16 + cq;
            float t00 = __expf(transitions[(c0 + 0) * Nn + r0]);
            float t01 = __expf(transitions[(c0 + 1) * Nn + r0]);
            float t10 = __expf(transitions[(c0 + 0) * Nn + r0 + 8]);
            float t11 = __expf(transitions[(c0 + 1) * Nn + r0 + 8]);
            float t02 = __expf(transitions[(c0 + 8) * Nn + r0]);
            float t03 = __expf(transitions[(c0 + 9) * Nn + r0]);
            float t12 = __expf(transitions[(c0 + 8) * Nn + r0 + 8]);
            float t13 = __expf(transitions[(c0 + 9) * Nn + r0 + 8]);
            A[mt][kt][0] = pkbf(t00, t01);
            A[mt][kt][1] = pkbf(t10, t11);
            A[mt][kt][2] = pkbf(t02, t03);
            A[mt][kt][3] = pkbf(t12, t13);
        }
    }

    const int len  = lengths[b];
    const int last = len - 1;

    // u0 into buffer 0 (permuted bf16, round-to-nearest once)
    ubuf[0][permb(j)] =
        __bfloat16_as_ushort(__float2bfloat16(__expf(start_t[j] + E[j])));

    // writers: lanes%4==0 own D column 0 rows {g, g+8, g+16, g+24}
    const bool writer = (lane & 3) == 0;
    const int rw0 = wid * 32 + g;
    const int pw0 = permb(rw0), pw1 = permb(rw0 + 8),
              pw2 = permb(rw0 + 16), pw3 = permb(rw0 + 24);

    // STRUNC = 1+2^-9 cancels the mean bias of bf16 truncation-rounding.
    const float STRUNC = 1.001953125f;

    // quad-split emission pipeline: even lanes of each quad handle rows
    // rw0+{0,8}, odd lanes rows rw0+{16,24}; writers receive the odd-lane
    // exps via shfl.down(1). peX/rawX serve odd steps, peY/rawY even steps.
    const int roff = (lane & 1) * 16;
    const float* Ew  = E + rw0;
    const float* EwQ = E + rw0 + roff;
    auto ldE = [&](int t, int off) {
        int tt = t > last ? last : t;
        return Ew[(size_t)tt * Nn + off];
    };
    float peX[4], peY[4];
#pragma unroll
    for (int c = 0; c < 4; ++c) {
        peX[c] = __expf(ldE(1, c * 8)) * STRUNC;
        peY[c] = __expf(ldE(2, c * 8)) * STRUNC;
    }
    float rawX[2], rawY[2];
    {
        auto ldQ = [&](int t, int off) {
            int tt = t > last ? last : t;
            return EwQ[(size_t)tt * Nn + off];
        };
        rawX[0] = ldQ(3, 0); rawX[1] = ldQ(3, 8);
        rawY[0] = ldQ(4, 0); rawY[1] = ldQ(4, 8);
    }

    const float pend = __expf(end_t[j]);
    float C  = 0.0f;                        // thread 0 only
    const float fz = 0.0f;                  // HMMA zero-C operand
    const float TGT      = 9.31322575e-10f; // 2^-30 renorm target
    const float LOG_ITGT = 20.7944154f;     // 30*ln2

    const uint32_t ub_addr = smem_u32(&ubuf[0][0]);
    uint32_t Bv[16];

    auto step = [&](int t, int rb, int wb, float* pe, float* raw) {
        __syncthreads();

        // ---- chain: UNCONDITIONAL broadcast load of permuted u_{t-1}.
        // Every lane loads the (lane&3) region; lanes 4-31 feed valid (but
        // unused) data into B cols 1-7. No branch envelope on the chain. ----
        {
            const uint32_t base = ub_addr
                                + (uint32_t)(rb * 256 + (lane & 3) * 64);
            asm volatile("ld.shared.v4.u32 {%0,%1,%2,%3}, [%4];"
                         : "=r"(Bv[0]), "=r"(Bv[1]), "=r"(Bv[2]), "=r"(Bv[3])
                         : "r"(base));
            asm volatile("ld.shared.v4.u32 {%0,%1,%2,%3}, [%4];"
                         : "=r"(Bv[4]), "=r"(Bv[5]), "=r"(Bv[6]), "=r"(Bv[7])
                         : "r"(base + 16));
            asm volatile("ld.shared.v4.u32 {%0,%1,%2,%3}, [%4];"
                         : "=r"(Bv[8]), "=r"(Bv[9]), "=r"(Bv[10]), "=r"(Bv[11])
                         : "r"(base + 32));
            asm volatile("ld.shared.v4.u32 {%0,%1,%2,%3}, [%4];"
                         : "=r"(Bv[12]), "=r"(Bv[13]), "=r"(Bv[14]), "=r"(Bv[15])
                         : "r"(base + 48));
        }

        // ==== LDS shadow: aux work issues while Bv is in flight ====
        float pe0 = pe[0], pe1 = pe[1], pe2 = pe[2], pe3 = pe[3];
        if ((t & 7) == 5) {                 // stale renorm fold (1/8 steps)
            float m4 = fmaxf(fmaxf(red[0], red[1]), fmaxf(red[2], red[3]));
            float rs = __fdividef(TGT, m4);
            pe0 *= rs; pe1 *= rs; pe2 *= rs; pe3 *= rs;
            if (j == 0) C += __logf(m4) + LOG_ITGT;
        }
        // quad-split regen: 2 MUFU per lane-role + 2 SHFL to the writer
        {
            float e0 = __expf(raw[0]) * STRUNC;   // this lane's 2 rows, t+2
            float e1 = __expf(raw[1]) * STRUNC;
            pe[0] = e0;
            pe[1] = e1;
            pe[2] = __shfl_down_sync(0xffffffffu, e0, 1);  // odd lane's rows
            pe[3] = __shfl_down_sync(0xffffffffu, e1, 1);
            int tt = t + 4; tt = tt > last ? last : tt;    // raw for t+4
            const float* Ep = EwQ + (size_t)tt * Nn;
            raw[0] = Ep[0]; raw[1] = Ep[8];
        }

        // ---- chain: 16 HMMA, 4 chains x 2 m-tiles; kt 0-3 seed with C=0 ----
        float acc[2][4][4];
#pragma unroll
        for (int kt = 0; kt < 4; ++kt) {
            mma_zc(acc[0][kt][0], acc[0][kt][1], acc[0][kt][2], acc[0][kt][3],
                   A[0][kt][0], A[0][kt][1], A[0][kt][2], A[0][kt][3],
                   Bv[2 * kt], Bv[2 * kt + 1], fz);
            mma_zc(acc[1][kt][0], acc[1][kt][1], acc[1][kt][2], acc[1][kt][3],
                   A[1][kt][0], A[1][kt][1], A[1][kt][2], A[1][kt][3],
                   Bv[2 * kt], Bv[2 * kt + 1], fz);
        }
#pragma unroll
        for (int kt = 4; kt < 8; ++kt) {
            mma_acc(acc[0][kt & 3][0], acc[0][kt & 3][1],
                    acc[0][kt & 3][2], acc[0][kt & 3][3],
                    A[0][kt][0], A[0][kt][1], A[0][kt][2], A[0][kt][3],
                    Bv[2 * kt], Bv[2 * kt + 1]);
            mma_acc(acc[1][kt & 3][0], acc[1][kt & 3][1],
                    acc[1][kt & 3][2], acc[1][kt & 3][3],
                    A[1][kt][0], A[1][kt][1], A[1][kt][2], A[1][kt][3],
                    Bv[2 * kt], Bv[2 * kt + 1]);
        }

        // ---- chain: epilogue ----
        float d0 = (acc[0][0][0] + acc[0][1][0]) + (acc[0][2][0] + acc[0][3][0]);
        float d1 = (acc[0][0][2] + acc[0][1][2]) + (acc[0][2][2] + acc[0][3][2]);
        float d2 = (acc[1][0][0] + acc[1][1][0]) + (acc[1][2][0] + acc[1][3][0]);
        float d3 = (acc[1][0][2] + acc[1][1][2]) + (acc[1][2][2] + acc[1][3][2]);
        float u0n = d0 * pe0, u1n = d1 * pe1;
        float u2n = d2 * pe2, u3n = d3 * pe3;
        if (writer) {
            // bf16 truncation store (bias pre-cancelled in pe)
            ubuf[wb][pw0] = (unsigned short)(__float_as_uint(u0n) >> 16);
            ubuf[wb][pw1] = (unsigned short)(__float_as_uint(u1n) >> 16);
            ubuf[wb][pw2] = (unsigned short)(__float_as_uint(u2n) >> 16);
            ubuf[wb][pw3] = (unsigned short)(__float_as_uint(u3n) >> 16);
        }

        // ---- tiny post-store tail: renorm publish only (1/8 steps) ----
        if ((t & 7) == 4) {
            if (lane == 0)
                red[wid] = fmaxf(fmaxf(u0n, u1n), fmaxf(u2n, u3n));
        }
    };

    int t = 1;
    for (; t + 1 <= last; t += 2) {
        step(t,     0, 1, peX, rawX);   // odd step
        step(t + 1, 1, 0, peY, rawY);   // even step
    }
    if (t <= last) step(t, 0, 1, peX, rawX);

    __syncthreads();

    // out[b] = log( sum_j u_last[j] * exp(end[j]) ) + C
    float u  = __uint_as_float((uint32_t)ubuf[last & 1][permb(j)] << 16);
    float ex = u * pend;
#pragma unroll
    for (int off = 16; off > 0; off >>= 1)
        ex += __shfl_xor_sync(0xffffffffu, ex, off);
    if (lane == 0) red[4 + wid] = ex;
    __syncthreads();
    if (j == 0)
        out[b] = __logf(red[4] + red[5] + red[6] + red[7]) + C;
}

extern "C" void kernel_launch(void* const* d_in, const int* in_sizes, int n_in,
                              void* d_out, int out_size) {
    const float* emissions   = (const float*)d_in[0];
    const float* transitions = (const float*)d_in[1];
    const float* start_t     = (const float*)d_in[2];
    const float* end_t       = (const float*)d_in[3];
    const int*   lengths     = (const int*)  d_in[4];
    crf_forward_kernel<<<Bb, Nn>>>(emissions, transitions, start_t, end_t,
                                   lengths, (float*)d_out);
}

// round 16
// speedup vs baseline: 1.2733x; 1.2733x over previous
#include <cuda_runtime.h>
#include <cuda_bf16.h>
#include <cstdint>

// CRF log-partition forward scan on tensor cores (mma.sync m16n8k16 bf16).
// B=64 batches, one block (128 threads / 4 warps = 1 per SMSP) per batch.
// Linear-domain recurrence u_t = diag(exp(e_t)) * expT^T * u_{t-1}.
// Chain: bar -> LDS.128 x4 (lanes 0-3 ONLY, permuted u; others keep Bv=0)
// -> [LDS shadow: (static-phase) renorm fold + quad-split exp regen
// (2 MUFU + 2 SHFL) + 2 LDG prefetch] -> 16 HMMA (4 chains x 2 m-tiles,
// C=0 seeded) -> add tree -> d*pe -> SHF>>16 bf16-truncation store (bias
// pre-cancelled via pe *= 1+2^-9) -> STS x4 -> (static-phase publish) -> bar.
// MAIN LOOP IS 8-STEP PHASE-SPECIALIZED: renorm branches compile away in
// 6 of 8 step bodies (no ISETP/BSSY on those chains). Remainder steps use
// a generic runtime-phase body. Renorm every 8 steps, stale, target 2^-30.

static constexpr int Bb = 64;
static constexpr int Ll = 512;
static constexpr int Nn = 128;

__device__ __forceinline__ uint32_t pkbf(float lo, float hi) {
    unsigned short l = __bfloat16_as_ushort(__float2bfloat16(lo));
    unsigned short h = __bfloat16_as_ushort(__float2bfloat16(hi));
    return (uint32_t)l | ((uint32_t)h << 16);
}

// b16 index of row r in the B-fragment-permuted u layout
__device__ __forceinline__ int permb(int r) {
    int kt = r >> 4, kr = r & 15;
    int half = kr >> 3, tsel = (kr & 7) >> 1, lohi = kr & 1;
    return tsel * 32 + kt * 4 + half * 2 + lohi;
}

__device__ __forceinline__ uint32_t smem_u32(const void* p) {
    uint32_t a;
    asm("{ .reg .u64 t; cvta.to.shared.u64 t, %1; cvt.u32.u64 %0, t; }"
        : "=r"(a) : "l"(p));
    return a;
}

// acc += A*B
__device__ __forceinline__ void mma_acc(float& d0, float& d1, float& d2, float& d3,
                                        uint32_t a0, uint32_t a1, uint32_t a2,
                                        uint32_t a3, uint32_t b0, uint32_t b1) {
    asm volatile(
        "mma.sync.aligned.m16n8k16.row.col.f32.bf16.bf16.f32 "
        "{%0,%1,%2,%3}, {%4,%5,%6,%7}, {%8,%9}, {%0,%1,%2,%3};"
        : "+f"(d0), "+f"(d1), "+f"(d2), "+f"(d3)
        : "r"(a0), "r"(a1), "r"(a2), "r"(a3), "r"(b0), "r"(b1));
}

// acc = A*B (C operand pinned to z: no accumulator-init MOVs)
__device__ __forceinline__ void mma_zc(float& d0, float& d1, float& d2, float& d3,
                                       uint32_t a0, uint32_t a1, uint32_t a2,
                                       uint32_t a3, uint32_t b0, uint32_t b1,
                                       float z) {
    asm volatile(
        "mma.sync.aligned.m16n8k16.row.col.f32.bf16.bf16.f32 "
        "{%0,%1,%2,%3}, {%4,%5,%6,%7}, {%8,%9}, {%10,%10,%10,%10};"
        : "=f"(d0), "=f"(d1), "=f"(d2), "=f"(d3)
        : "r"(a0), "r"(a1), "r"(a2), "r"(a3), "r"(b0), "r"(b1), "f"(z));
}

// One scan step. DOFOLD / DOPUB are literal 0/1 -> branches fold at compile
// time in the specialized main loop.
#define STEP(tcur, rb, wb, pe, raw, DOFOLD, DOPUB) do {                       \
    __syncthreads();                                                          \
    if (lane < 4) {                                                           \
        const uint32_t base_ = ub_addr + (uint32_t)((rb) * 256 + lane * 64);  \
        asm volatile("ld.shared.v4.u32 {%0,%1,%2,%3}, [%4];"                  \
                     : "=r"(Bv[0]), "=r"(Bv[1]), "=r"(Bv[2]), "=r"(Bv[3])     \
                     : "r"(base_));                                           \
        asm volatile("ld.shared.v4.u32 {%0,%1,%2,%3}, [%4];"                  \
                     : "=r"(Bv[4]), "=r"(Bv[5]), "=r"(Bv[6]), "=r"(Bv[7])     \
                     : "r"(base_ + 16));                                      \
        asm volatile("ld.shared.v4.u32 {%0,%1,%2,%3}, [%4];"                  \
                     : "=r"(Bv[8]), "=r"(Bv[9]), "=r"(Bv[10]), "=r"(Bv[11])   \
                     : "r"(base_ + 32));                                      \
        asm volatile("ld.shared.v4.u32 {%0,%1,%2,%3}, [%4];"                  \
                     : "=r"(Bv[12]), "=r"(Bv[13]), "=r"(Bv[14]), "=r"(Bv[15]) \
                     : "r"(base_ + 48));                                      \
    }                                                                         \
    float pe0 = (pe)[0], pe1 = (pe)[1], pe2 = (pe)[2], pe3 = (pe)[3];         \
    if (DOFOLD) {                                                             \
        float m4_ = fmaxf(fmaxf(red[0], red[1]), fmaxf(red[2], red[3]));      \
        float rs_ = __fdividef(TGT, m4_);                                     \
        pe0 *= rs_; pe1 *= rs_; pe2 *= rs_; pe3 *= rs_;                       \
        if (j == 0) C += __logf(m4_) + LOG_ITGT;                              \
    }                                                                         \
    {                                                                         \
        float e0_ = __expf((raw)[0]) * STRUNC;                                \
        float e1_ = __expf((raw)[1]) * STRUNC;                                \
        (pe)[0] = e0_;                                                        \
        (pe)[1] = e1_;                                                        \
        (pe)[2] = __shfl_down_sync(0xffffffffu, e0_, 1);                      \
        (pe)[3] = __shfl_down_sync(0xffffffffu, e1_, 1);                      \
        int tt_ = (tcur) + 4; tt_ = tt_ > last ? last : tt_;                  \
        const float* Ep_ = EwQ + (size_t)tt_ * Nn;                            \
        (raw)[0] = Ep_[0]; (raw)[1] = Ep_[8];                                 \
    }                                                                         \
    float acc[2][4][4];                                                       \
    _Pragma("unroll")                                                         \
    for (int kt = 0; kt < 4; ++kt) {                                          \
        mma_zc(acc[0][kt][0], acc[0][kt][1], acc[0][kt][2], acc[0][kt][3],    \
               A[0][kt][0], A[0][kt][1], A[0][kt][2], A[0][kt][3],            \
               Bv[2 * kt], Bv[2 * kt + 1], fz);                               \
        mma_zc(acc[1][kt][0], acc[1][kt][1], acc[1][kt][2], acc[1][kt][3],    \
               A[1][kt][0], A[1][kt][1], A[1][kt][2], A[1][kt][3],            \
               Bv[2 * kt], Bv[2 * kt + 1], fz);                               \
    }                                                                         \
    _Pragma("unroll")                                                         \
    for (int kt = 4; kt < 8; ++kt) {                                          \
        mma_acc(acc[0][kt & 3][0], acc[0][kt & 3][1],                         \
                acc[0][kt & 3][2], acc[0][kt & 3][3],                         \
                A[0][kt][0], A[0][kt][1], A[0][kt][2], A[0][kt][3],           \
                Bv[2 * kt], Bv[2 * kt + 1]);                                  \
        mma_acc(acc[1][kt & 3][0], acc[1][kt & 3][1],                         \
                acc[1][kt & 3][2], acc[1][kt & 3][3],                         \
                A[1][kt][0], A[1][kt][1], A[1][kt][2], A[1][kt][3],           \
                Bv[2 * kt], Bv[2 * kt + 1]);                                  \
    }                                                                         \
    float d0 = (acc[0][0][0] + acc[0][1][0]) + (acc[0][2][0] + acc[0][3][0]); \
    float d1 = (acc[0][0][2] + acc[0][1][2]) + (acc[0][2][2] + acc[0][3][2]); \
    float d2 = (acc[1][0][0] + acc[1][1][0]) + (acc[1][2][0] + acc[1][3][0]); \
    float d3 = (acc[1][0][2] + acc[1][1][2]) + (acc[1][2][2] + acc[1][3][2]); \
    float u0n = d0 * pe0, u1n = d1 * pe1;                                     \
    float u2n = d2 * pe2, u3n = d3 * pe3;                                     \
    if (writer) {                                                             \
        ubuf[wb][pw0] = (unsigned short)(__float_as_uint(u0n) >> 16);         \
        ubuf[wb][pw1] = (unsigned short)(__float_as_uint(u1n) >> 16);         \
        ubuf[wb][pw2] = (unsigned short)(__float_as_uint(u2n) >> 16);         \
        ubuf[wb][pw3] = (unsigned short)(__float_as_uint(u3n) >> 16);         \
    }                                                                         \
    if (DOPUB) {                                                              \
        if (lane == 0)                                                        \
            red[wid] = fmaxf(fmaxf(u0n, u1n), fmaxf(u2n, u3n));               \
    }                                                                         \
} while (0)

__global__ __launch_bounds__(128, 1)
void crf_forward_kernel(const float* __restrict__ emissions,
                        const float* __restrict__ transitions,
                        const float* __restrict__ start_t,
                        const float* __restrict__ end_t,
                        const int*   __restrict__ lengths,
                        float*       __restrict__ out)
{
    const int b    = blockIdx.x;
    const int j    = threadIdx.x;
    const int lane = j & 31;
    const int wid  = j >> 5;

    __shared__ __align__(16) unsigned short ubuf[2][Nn];  // bf16 bits, permuted
    __shared__ float red[8];   // [0..3] renorm samples, [4..7] final reduce

    const float* E = emissions + (size_t)b * Ll * Nn;

    // ---- stationary A fragments: A[m][k] = exp(transitions[k][m]) ----
    const int g  = lane >> 2;
    const int cq = (lane & 3) * 2;
    uint32_t A[2][8][4];
#pragma unroll
    for (int mt = 0; mt < 2; ++mt) {
        const int r0 = wid * 32 + mt * 16 + g;
#pragma unroll
        for (int kt = 0; kt < 8; ++kt) {
            const int c0 = kt * 16 + cq;
            float t00 = __expf(transitions[(c0 + 0) * Nn + r0]);
            float t01 = __expf(transitions[(c0 + 1) * Nn + r0]);
            float t10 = __expf(transitions[(c0 + 0) * Nn + r0 + 8]);
            float t11 = __expf(transitions[(c0 + 1) * Nn + r0 + 8]);
            float t02 = __expf(transitions[(c0 + 8) * Nn + r0]);
            float t03 = __expf(transitions[(c0 + 9) * Nn + r0]);
            float t12 = __expf(transitions[(c0 + 8) * Nn + r0 + 8]);
            float t13 = __expf(transitions[(c0 + 9) * Nn + r0 + 8]);
            A[mt][kt][0] = pkbf(t00, t01);
            A[mt][kt][1] = pkbf(t10, t11);
            A[mt][kt][2] = pkbf(t02, t03);
            A[mt][kt][3] = pkbf(t12, t13);
        }
    }

    const int len  = lengths[b];
    const int last = len - 1;

    // u0 into buffer 0 (permuted bf16, round-to-nearest once)
    ubuf[0][permb(j)] =
        __bfloat16_as_ushort(__float2bfloat16(__expf(start_t[j] + E[j])));

    // writers: lanes%4==0 own D column 0 rows {g, g+8, g+16, g+24}
    const bool writer = (lane & 3) == 0;
    const int rw0 = wid * 32 + g;
    const int pw0 = permb(rw0), pw1 = permb(rw0 + 8),
              pw2 = permb(rw0 + 16), pw3 = permb(rw0 + 24);

    // STRUNC = 1+2^-9 cancels the mean bias of bf16 truncation-rounding.
    const float STRUNC = 1.001953125f;

    // quad-split emission pipeline: even lanes of each quad handle rows
    // rw0+{0,8}, odd lanes rows rw0+{16,24}; writers receive the odd-lane
    // exps via shfl.down(1). peX/rawX serve odd steps, peY/rawY even steps.
    const int roff = (lane & 1) * 16;
    const float* Ew  = E + rw0;
    const float* EwQ = E + rw0 + roff;
    auto ldE = [&](int t, int off) {
        int tt = t > last ? last : t;
        return Ew[(size_t)tt * Nn + off];
    };
    float peX[4], peY[4];
#pragma unroll
    for (int c = 0; c < 4; ++c) {
        peX[c] = __expf(ldE(1, c * 8)) * STRUNC;
        peY[c] = __expf(ldE(2, c * 8)) * STRUNC;
    }
    float rawX[2], rawY[2];
    {
        auto ldQ = [&](int t, int off) {
            int tt = t > last ? last : t;
            return EwQ[(size_t)tt * Nn + off];
        };
        rawX[0] = ldQ(3, 0); rawX[1] = ldQ(3, 8);
        rawY[0] = ldQ(4, 0); rawY[1] = ldQ(4, 8);
    }

    const float pend = __expf(end_t[j]);
    float C  = 0.0f;                        // thread 0 only
    const float fz = 0.0f;                  // HMMA zero-C operand
    const float TGT      = 9.31322575e-10f; // 2^-30 renorm target
    const float LOG_ITGT = 20.7944154f;     // 30*ln2

    const uint32_t ub_addr = smem_u32(&ubuf[0][0]);
    uint32_t Bv[16] = {0,0,0,0,0,0,0,0,0,0,0,0,0,0,0,0};

    // ---- main loop: 8-step chunks with static phases ----
    // t starts at 1, so position p in the chunk has phase (1+p)&7:
    // publish (phase 4) at p=3, fold (phase 5) at p=4.
    int t = 1;
    for (; t + 7 <= last; t += 8) {
        STEP(t + 0, 0, 1, peX, rawX, 0, 0);  // phase 1
        STEP(t + 1, 1, 0, peY, rawY, 0, 0);  // phase 2
        STEP(t + 2, 0, 1, peX, rawX, 0, 0);  // phase 3
        STEP(t + 3, 1, 0, peY, rawY, 0, 1);  // phase 4: publish
        STEP(t + 4, 0, 1, peX, rawX, 1, 0);  // phase 5: fold
        STEP(t + 5, 1, 0, peY, rawY, 0, 0);  // phase 6
        STEP(t + 6, 0, 1, peX, rawX, 0, 0);  // phase 7
        STEP(t + 7, 1, 0, peY, rawY, 0, 0);  // phase 0
    }
    // ---- remainder: generic runtime-phase steps ----
    for (; t <= last; ++t) {
        const int fold = ((t & 7) == 5);
        const int pub  = ((t & 7) == 4);
        if (t & 1) STEP(t, 0, 1, peX, rawX, fold, pub);
        else       STEP(t, 1, 0, peY, rawY, fold, pub);
    }

    __syncthreads();

    // out[b] = log( sum_j u_last[j] * exp(end[j]) ) + C
    float u  = __uint_as_float((uint32_t)ubuf[last & 1][permb(j)] << 16);
    float ex = u * pend;
#pragma unroll
    for (int off = 16; off > 0; off >>= 1)
        ex += __shfl_xor_sync(0xffffffffu, ex, off);
    if (lane == 0) red[4 + wid] = ex;
    __syncthreads();
    if (j == 0)
        out[b] = __logf(red[4] + red[5] + red[6] + red[7]) + C;
}

extern "C" void kernel_launch(void* const* d_in, const int* in_sizes, int n_in,
                              void* d_out, int out_size) {
    const float* emissions   = (const float*)d_in[0];
    const float* transitions = (const float*)d_in[1];
    const float* start_t     = (const float*)d_in[2];
    const float* end_t       = (const float*)d_in[3];
    const int*   lengths     = (const int*)  d_in[4];
    crf_forward_kernel<<<Bb, Nn>>>(emissions, transitions, start_t, end_t,
                                   lengths, (float*)d_out);
}